// round 8
// baseline (speedup 1.0000x reference)
#include <cuda_runtime.h>

// CSPN 7x7 guided propagation, v4: smem hn tile + 4 output rows per thread.
// out[b,y,x] = sum_{i,j in [0,7)} gw[b, i*7+j, y+3, x+3] * src[b, y+3-i, x+3-j]
//   src = h0 for tap 24 (i=j=3), hn otherwise; zero outside [0,512).
//
// guide_weight: (8, 49, 518, 518) f32   -> streamed once (~421 MB), DRAM-bound
// hn:           (8, 1, 512, 512)  f32   -> 48x reuse, staged in padded smem
// h0:           (8, 1, 512, 512)  f32   -> single direct load (center tap)
// out:          (8, 1, 512, 512)  f32
//
// v4: each thread computes rows (y, y+8, y+16, y+24) of a 32x32 tile.
// Per tap: 4 gw loads off one base reg + const-imm offsets -> 2x v3's
// per-warp in-flight load window, keeping the DRAM queue full across the
// FMA tails. Reg budget ~85 via __launch_bounds__(256, 3).

#define KK 7
#define HW 512
#define PW 518              // padded width/height (512 + 6)
#define PLANE (PW * PW)     // elements per (b, tap) plane

#define TW 32               // tile width (threads x)
#define THY 8               // threads y
#define RY 4                // output rows per thread
#define TILE_H (THY * RY)   // 32
#define SW (TW + 6)         // 38
#define SH (TILE_H + 6)     // 38
#define SELEMS (SW * SH)    // 1444

__global__ __launch_bounds__(256, 3) void cspn_kernel(
    const float* __restrict__ gw,
    const float* __restrict__ hn,
    const float* __restrict__ h0,
    float* __restrict__ out)
{
    __shared__ float s[SH][SW];

    const int tx = threadIdx.x;
    const int ty = threadIdx.y;
    const int x  = blockIdx.x * TW + tx;
    const int y0 = blockIdx.y * TILE_H + ty;   // rows y0 + {0,8,16,24}
    const int b  = blockIdx.z;

    const float* hnp = hn + (long)b * HW * HW;

    // ---- fill padded hn tile (zero outside [0,512)^2) ----
    {
        const int row0 = blockIdx.y * TILE_H - 3;
        const int col0 = blockIdx.x * TW - 3;
        const int tid = ty * TW + tx;
        #pragma unroll
        for (int idx = 0; idx < SELEMS; idx += TW * THY) {
            int k = idx + tid;
            if (k < SELEMS) {
                int r = k / SW;
                int c = k - r * SW;
                int gr = row0 + r;
                int gc = col0 + c;
                float v = 0.0f;
                if ((unsigned)gr < (unsigned)HW && (unsigned)gc < (unsigned)HW)
                    v = __ldg(hnp + gr * HW + gc);
                s[r][c] = v;
            }
        }
    }
    __syncthreads();

    // per-batch gw base; 32-bit offsets within a batch (52.6 MB < 2^31 bytes)
    const float* gwb = gw + (long)b * 49 * PLANE;
    const int base0 = (y0 + 3) * PW + (x + 3);   // tap-0 offset for row y0

    // center tap (h0) for all rows
    const long ob = ((long)b * HW + y0) * HW + x;
    float acc0 = __ldg(gwb + 24 * PLANE + base0)           * __ldg(h0 + ob);
    float acc1 = __ldg(gwb + 24 * PLANE + base0 + 8 * PW)  * __ldg(h0 + ob + 8 * HW);
    float acc2 = __ldg(gwb + 24 * PLANE + base0 + 16 * PW) * __ldg(h0 + ob + 16 * HW);
    float acc3 = __ldg(gwb + 24 * PLANE + base0 + 24 * PW) * __ldg(h0 + ob + 24 * HW);

#pragma unroll
    for (int i = 0; i < KK; ++i) {
        const int sr = ty + 6 - i;           // smem row for output row y0
#pragma unroll
        for (int j = 0; j < KK; ++j) {
            const int t = i * KK + j;
            if (t == 24) continue;           // center handled above (h0)
            const int off = t * PLANE + base0;
            const float g0 = __ldg(gwb + off);
            const float g1 = __ldg(gwb + off + 8 * PW);
            const float g2 = __ldg(gwb + off + 16 * PW);
            const float g3 = __ldg(gwb + off + 24 * PW);
            const int sc = tx + 6 - j;
            acc0 = fmaf(g0, s[sr][sc],      acc0);
            acc1 = fmaf(g1, s[sr + 8][sc],  acc1);
            acc2 = fmaf(g2, s[sr + 16][sc], acc2);
            acc3 = fmaf(g3, s[sr + 24][sc], acc3);
        }
    }

    out[ob]           = acc0;
    out[ob + 8 * HW]  = acc1;
    out[ob + 16 * HW] = acc2;
    out[ob + 24 * HW] = acc3;
}

extern "C" void kernel_launch(void* const* d_in, const int* in_sizes, int n_in,
                              void* d_out, int out_size)
{
    const float* gw = (const float*)d_in[0];  // (8, 49, 518, 518)
    const float* hn = (const float*)d_in[1];  // (8, 1, 512, 512)
    const float* h0 = (const float*)d_in[2];  // (8, 1, 512, 512)
    float* out = (float*)d_out;               // (8, 1, 512, 512)

    dim3 block(TW, THY, 1);
    dim3 grid(HW / TW, HW / TILE_H, 8);
    cspn_kernel<<<grid, block>>>(gw, hn, h0, out);
}

// round 9
// speedup vs baseline: 1.0256x; 1.0256x over previous
#include <cuda_runtime.h>

// CSPN 7x7 guided propagation, v5: v3 structure (smem hn tile, 2 rows/thread)
// with a 48-register cap to lift occupancy 30 -> 40 warps/SM.
//
// out[b,y,x] = sum_{i,j in [0,7)} gw[b, i*7+j, y+3, x+3] * src[b, y+3-i, x+3-j]
//   src = h0 for tap 24 (i=j=3), hn otherwise; zero outside [0,512).
//
// guide_weight: (8, 49, 518, 518) f32   -> streamed once (~421 MB), DRAM-bound
// hn:           (8, 1, 512, 512)  f32   -> 48x reuse, staged in padded smem
// h0:           (8, 1, 512, 512)  f32   -> single direct load (center tap)
// out:          (8, 1, 512, 512)  f32

#define KK 7
#define HW 512
#define PW 518              // padded width/height (512 + 6)
#define PLANE (PW * PW)     // elements per (b, tap) plane

#define TW 32               // tile width (threads x)
#define THY 8               // threads y
#define RY 2                // output rows per thread
#define TILE_H (THY * RY)   // 16
#define SW (TW + 6)         // 38
#define SH (TILE_H + 6)     // 22
#define SELEMS (SW * SH)    // 836

__global__ __launch_bounds__(256, 5) void cspn_kernel(
    const float* __restrict__ gw,
    const float* __restrict__ hn,
    const float* __restrict__ h0,
    float* __restrict__ out)
{
    __shared__ float s[SH][SW];

    const int tx = threadIdx.x;
    const int ty = threadIdx.y;
    const int x  = blockIdx.x * TW + tx;
    const int y0 = blockIdx.y * TILE_H + ty;   // first output row (second is y0+8)
    const int b  = blockIdx.z;

    const float* hnp = hn + (long)b * HW * HW;

    // ---- fill padded hn tile (zero outside [0,512)^2) ----
    {
        const int row0 = blockIdx.y * TILE_H - 3;
        const int col0 = blockIdx.x * TW - 3;
        const int tid = ty * TW + tx;
        #pragma unroll
        for (int idx = 0; idx < SELEMS; idx += TW * THY) {
            int k = idx + tid;
            if (k < SELEMS) {
                int r = k / SW;
                int c = k - r * SW;
                int gr = row0 + r;
                int gc = col0 + c;
                float v = 0.0f;
                if ((unsigned)gr < (unsigned)HW && (unsigned)gc < (unsigned)HW)
                    v = __ldg(hnp + gr * HW + gc);
                s[r][c] = v;
            }
        }
    }
    __syncthreads();

    // per-batch gw base; 32-bit offsets within a batch (52.6 MB < 2^31 bytes)
    const float* gwb = gw + (long)b * 49 * PLANE;
    const int base0 = (y0 + 3) * PW + (x + 3);   // tap-0 offset for row y0

    // center tap (h0) for both rows
    const long ob = ((long)b * HW + y0) * HW + x;
    float acc0 = __ldg(gwb + 24 * PLANE + base0)          * __ldg(h0 + ob);
    float acc1 = __ldg(gwb + 24 * PLANE + base0 + 8 * PW) * __ldg(h0 + ob + 8 * HW);

#pragma unroll
    for (int i = 0; i < KK; ++i) {
        const int sr0 = ty + 6 - i;          // smem row for output row y0
        const int sr1 = sr0 + 8;             // smem row for output row y0+8
#pragma unroll
        for (int j = 0; j < KK; ++j) {
            const int t = i * KK + j;
            if (t == 24) continue;           // center handled above (h0)
            const int off = t * PLANE + base0;
            const float g0 = __ldg(gwb + off);
            const float g1 = __ldg(gwb + off + 8 * PW);
            const int sc = tx + 6 - j;
            acc0 = fmaf(g0, s[sr0][sc], acc0);
            acc1 = fmaf(g1, s[sr1][sc], acc1);
        }
    }

    out[ob]          = acc0;
    out[ob + 8 * HW] = acc1;
}

extern "C" void kernel_launch(void* const* d_in, const int* in_sizes, int n_in,
                              void* d_out, int out_size)
{
    const float* gw = (const float*)d_in[0];  // (8, 49, 518, 518)
    const float* hn = (const float*)d_in[1];  // (8, 1, 512, 512)
    const float* h0 = (const float*)d_in[2];  // (8, 1, 512, 512)
    float* out = (float*)d_out;               // (8, 1, 512, 512)

    dim3 block(TW, THY, 1);
    dim3 grid(HW / TW, HW / TILE_H, 8);
    cspn_kernel<<<grid, block>>>(gw, hn, h0, out);
}

// round 10
// speedup vs baseline: 1.0854x; 1.0583x over previous
#include <cuda_runtime.h>

// CSPN 7x7 guided propagation, v6: v5 + streaming cache policy.
// Single-variable change from v5: gw loads use __ldcs (evict-first; zero
// reuse stream, keep it out of L2's way), out stores use __stcs. hn/h0
// keep __ldg (real reuse). Structure, tiling, launch identical to v5.
//
// out[b,y,x] = sum_{i,j in [0,7)} gw[b, i*7+j, y+3, x+3] * src[b, y+3-i, x+3-j]
//   src = h0 for tap 24 (i=j=3), hn otherwise; zero outside [0,512).
//
// guide_weight: (8, 49, 518, 518) f32   -> streamed once (~412 MB read)
// hn:           (8, 1, 512, 512)  f32   -> 48x reuse, staged in padded smem
// h0:           (8, 1, 512, 512)  f32   -> single direct load (center tap)
// out:          (8, 1, 512, 512)  f32   -> streamed write

#define KK 7
#define HW 512
#define PW 518              // padded width/height (512 + 6)
#define PLANE (PW * PW)     // elements per (b, tap) plane

#define TW 32               // tile width (threads x)
#define THY 8               // threads y
#define RY 2                // output rows per thread
#define TILE_H (THY * RY)   // 16
#define SW (TW + 6)         // 38
#define SH (TILE_H + 6)     // 22
#define SELEMS (SW * SH)    // 836

__global__ __launch_bounds__(256, 5) void cspn_kernel(
    const float* __restrict__ gw,
    const float* __restrict__ hn,
    const float* __restrict__ h0,
    float* __restrict__ out)
{
    __shared__ float s[SH][SW];

    const int tx = threadIdx.x;
    const int ty = threadIdx.y;
    const int x  = blockIdx.x * TW + tx;
    const int y0 = blockIdx.y * TILE_H + ty;   // first output row (second is y0+8)
    const int b  = blockIdx.z;

    const float* hnp = hn + (long)b * HW * HW;

    // ---- fill padded hn tile (zero outside [0,512)^2) ----
    {
        const int row0 = blockIdx.y * TILE_H - 3;
        const int col0 = blockIdx.x * TW - 3;
        const int tid = ty * TW + tx;
        #pragma unroll
        for (int idx = 0; idx < SELEMS; idx += TW * THY) {
            int k = idx + tid;
            if (k < SELEMS) {
                int r = k / SW;
                int c = k - r * SW;
                int gr = row0 + r;
                int gc = col0 + c;
                float v = 0.0f;
                if ((unsigned)gr < (unsigned)HW && (unsigned)gc < (unsigned)HW)
                    v = __ldg(hnp + gr * HW + gc);
                s[r][c] = v;
            }
        }
    }
    __syncthreads();

    // per-batch gw base; 32-bit offsets within a batch (52.6 MB < 2^31 bytes)
    const float* gwb = gw + (long)b * 49 * PLANE;
    const int base0 = (y0 + 3) * PW + (x + 3);   // tap-0 offset for row y0

    // center tap (h0) for both rows
    const long ob = ((long)b * HW + y0) * HW + x;
    float acc0 = __ldcs(gwb + 24 * PLANE + base0)          * __ldg(h0 + ob);
    float acc1 = __ldcs(gwb + 24 * PLANE + base0 + 8 * PW) * __ldg(h0 + ob + 8 * HW);

#pragma unroll
    for (int i = 0; i < KK; ++i) {
        const int sr0 = ty + 6 - i;          // smem row for output row y0
        const int sr1 = sr0 + 8;             // smem row for output row y0+8
#pragma unroll
        for (int j = 0; j < KK; ++j) {
            const int t = i * KK + j;
            if (t == 24) continue;           // center handled above (h0)
            const int off = t * PLANE + base0;
            const float g0 = __ldcs(gwb + off);
            const float g1 = __ldcs(gwb + off + 8 * PW);
            const int sc = tx + 6 - j;
            acc0 = fmaf(g0, s[sr0][sc], acc0);
            acc1 = fmaf(g1, s[sr1][sc], acc1);
        }
    }

    __stcs(out + ob,          acc0);
    __stcs(out + ob + 8 * HW, acc1);
}

extern "C" void kernel_launch(void* const* d_in, const int* in_sizes, int n_in,
                              void* d_out, int out_size)
{
    const float* gw = (const float*)d_in[0];  // (8, 49, 518, 518)
    const float* hn = (const float*)d_in[1];  // (8, 1, 512, 512)
    const float* h0 = (const float*)d_in[2];  // (8, 1, 512, 512)
    float* out = (float*)d_out;               // (8, 1, 512, 512)

    dim3 block(TW, THY, 1);
    dim3 grid(HW / TW, HW / TILE_H, 8);
    cspn_kernel<<<grid, block>>>(gw, hn, h0, out);
}